// round 1
// baseline (speedup 1.0000x reference)
#include <cuda_runtime.h>

// ---------------------------------------------------------------------------
// Problem: B=8, S=2048, D=512 single-head self-attention, fp32.
// out = softmax((xWq+bq)(xWk+bk)^T / sqrt(D)) (xWv+bv) * mask[:, :, None]
// ---------------------------------------------------------------------------

#define Bsz 8
#define Sq  2048
#define Dd  512

// Scratch (allocation-free rule: __device__ globals)
__device__ float g_q[Bsz * Sq * Dd];
__device__ float g_k[Bsz * Sq * Dd];
__device__ float g_v[Bsz * Sq * Dd];
__device__ float g_s[(size_t)Bsz * Sq * Sq];

// ---------------------------------------------------------------------------
// 128x128x8 fp32 tiled GEMM mainloop, 256 threads, 8x8 micro-tile per thread.
// A: [M x K] row-major (lda = K stride). blockIdx.y selects 128-row tile.
// B: NN: [K x N] row-major (ldb);  NT: [N x K] row-major (ldb).
// blockIdx.x selects 128-col tile. All dims assumed multiples of tile sizes.
// ---------------------------------------------------------------------------
template <bool TRANSB>
__device__ __forceinline__ void gemm_main(const float* __restrict__ A,
                                          const float* __restrict__ B,
                                          int K, int lda, int ldb,
                                          float (&acc)[8][8]) {
    __shared__ float sA[8 * 128];
    __shared__ float sB[8 * 128];

    const int tid = threadIdx.x;
    const int m0 = blockIdx.y * 128;
    const int n0 = blockIdx.x * 128;
    const int ty = tid >> 4;       // 0..15
    const int tx = tid & 15;       // 0..15

    // A-style loader: 128 rows x 8 k, one float4 per thread
    const int arow = tid >> 1;         // 0..127
    const int acol = (tid & 1) * 4;    // 0 or 4
    // NN B loader: 8 k-rows x 128 n-cols
    const int brow = tid >> 5;         // 0..7
    const int bcol = (tid & 31) * 4;   // 0..124

#pragma unroll
    for (int i = 0; i < 8; i++)
#pragma unroll
        for (int j = 0; j < 8; j++) acc[i][j] = 0.0f;

    for (int k0 = 0; k0 < K; k0 += 8) {
        // load A tile, store transposed sA[k][m]
        float4 av = *(const float4*)(A + (size_t)(m0 + arow) * lda + (k0 + acol));
        sA[(acol + 0) * 128 + arow] = av.x;
        sA[(acol + 1) * 128 + arow] = av.y;
        sA[(acol + 2) * 128 + arow] = av.z;
        sA[(acol + 3) * 128 + arow] = av.w;

        if (TRANSB) {
            // B is [N x K]; tile = 128 n-rows x 8 k-cols; store sB[k][n]
            float4 bv = *(const float4*)(B + (size_t)(n0 + arow) * ldb + (k0 + acol));
            sB[(acol + 0) * 128 + arow] = bv.x;
            sB[(acol + 1) * 128 + arow] = bv.y;
            sB[(acol + 2) * 128 + arow] = bv.z;
            sB[(acol + 3) * 128 + arow] = bv.w;
        } else {
            // B is [K x N]; tile = 8 k-rows x 128 n-cols; direct copy
            float4 bv = *(const float4*)(B + (size_t)(k0 + brow) * ldb + (n0 + bcol));
            *(float4*)(sB + brow * 128 + bcol) = bv;
        }
        __syncthreads();

#pragma unroll
        for (int kk = 0; kk < 8; kk++) {
            float a[8], b[8];
            *(float4*)(a)     = *(const float4*)(sA + kk * 128 + ty * 8);
            *(float4*)(a + 4) = *(const float4*)(sA + kk * 128 + ty * 8 + 4);
            *(float4*)(b)     = *(const float4*)(sB + kk * 128 + tx * 8);
            *(float4*)(b + 4) = *(const float4*)(sB + kk * 128 + tx * 8 + 4);
#pragma unroll
            for (int i = 0; i < 8; i++)
#pragma unroll
                for (int j = 0; j < 8; j++)
                    acc[i][j] = fmaf(a[i], b[j], acc[i][j]);
        }
        __syncthreads();
    }
}

// ---------------------------------------------------------------------------
// Kernel 1: fused Q/K/V projection. blockIdx.z in {0,1,2} selects weight set.
// C[16384, 512] = x[16384, 512] @ W[512, 512] + b
// grid (512/128=4, 16384/128=128, 3), 256 threads
// ---------------------------------------------------------------------------
__global__ __launch_bounds__(256) void qkv_proj_kernel(
    const float* __restrict__ x,
    const float* __restrict__ Wq, const float* __restrict__ bq,
    const float* __restrict__ Wk, const float* __restrict__ bk,
    const float* __restrict__ Wv, const float* __restrict__ bv) {
    const float* W;
    const float* bias;
    float* out;
    if (blockIdx.z == 0)      { W = Wq; bias = bq; out = g_q; }
    else if (blockIdx.z == 1) { W = Wk; bias = bk; out = g_k; }
    else                      { W = Wv; bias = bv; out = g_v; }

    float acc[8][8];
    gemm_main<false>(x, W, Dd, Dd, Dd, acc);

    const int m0 = blockIdx.y * 128, n0 = blockIdx.x * 128;
    const int ty = threadIdx.x >> 4, tx = threadIdx.x & 15;
#pragma unroll
    for (int i = 0; i < 8; i++) {
        const int m = m0 + ty * 8 + i;
#pragma unroll
        for (int j = 0; j < 8; j += 4) {
            const int n = n0 + tx * 8 + j;
            float4 r;
            r.x = acc[i][j + 0] + bias[n + 0];
            r.y = acc[i][j + 1] + bias[n + 1];
            r.z = acc[i][j + 2] + bias[n + 2];
            r.w = acc[i][j + 3] + bias[n + 3];
            *(float4*)(out + (size_t)m * Dd + n) = r;
        }
    }
}

// ---------------------------------------------------------------------------
// Kernel 2: scores = Q @ K^T / sqrt(D), per batch.
// grid (2048/128=16, 2048/128=16, 8), 256 threads
// ---------------------------------------------------------------------------
__global__ __launch_bounds__(256) void scores_kernel() {
    const int b = blockIdx.z;
    const float* Q  = g_q + (size_t)b * Sq * Dd;
    const float* Kp = g_k + (size_t)b * Sq * Dd;
    float* Sp = g_s + (size_t)b * Sq * Sq;

    float acc[8][8];
    gemm_main<true>(Q, Kp, Dd, Dd, Dd, acc);

    const float scale = 0.04419417382415922f;  // 1/sqrt(512)
    const int m0 = blockIdx.y * 128, n0 = blockIdx.x * 128;
    const int ty = threadIdx.x >> 4, tx = threadIdx.x & 15;
#pragma unroll
    for (int i = 0; i < 8; i++) {
        const int m = m0 + ty * 8 + i;
#pragma unroll
        for (int j = 0; j < 8; j += 4) {
            const int n = n0 + tx * 8 + j;
            float4 r;
            r.x = acc[i][j + 0] * scale;
            r.y = acc[i][j + 1] * scale;
            r.z = acc[i][j + 2] * scale;
            r.w = acc[i][j + 3] * scale;
            *(float4*)(Sp + (size_t)m * Sq + n) = r;
        }
    }
}

// ---------------------------------------------------------------------------
// Kernel 3: row softmax over scores. One block (256 thr) per row.
// grid (2048, 8)
// ---------------------------------------------------------------------------
__global__ __launch_bounds__(256) void softmax_kernel() {
    const int b = blockIdx.y;
    float* row = g_s + ((size_t)b * Sq + blockIdx.x) * Sq;
    const int tid = threadIdx.x;
    const int lane = tid & 31;
    const int warp = tid >> 5;

    __shared__ float red[8];
    __shared__ float s_bcast;

    float v[8];
    *(float4*)(v)     = *(const float4*)(row + tid * 8);
    *(float4*)(v + 4) = *(const float4*)(row + tid * 8 + 4);

    // --- row max ---
    float m = v[0];
#pragma unroll
    for (int i = 1; i < 8; i++) m = fmaxf(m, v[i]);
#pragma unroll
    for (int off = 16; off; off >>= 1)
        m = fmaxf(m, __shfl_xor_sync(0xffffffffu, m, off));
    if (lane == 0) red[warp] = m;
    __syncthreads();
    if (tid < 8) {
        float t = red[tid];
#pragma unroll
        for (int off = 4; off; off >>= 1)
            t = fmaxf(t, __shfl_xor_sync(0xffu, t, off));
        if (tid == 0) s_bcast = t;
    }
    __syncthreads();
    const float rowmax = s_bcast;

    // --- exp + row sum ---
    float sum = 0.0f;
#pragma unroll
    for (int i = 0; i < 8; i++) {
        v[i] = __expf(v[i] - rowmax);
        sum += v[i];
    }
#pragma unroll
    for (int off = 16; off; off >>= 1)
        sum += __shfl_xor_sync(0xffffffffu, sum, off);
    __syncthreads();  // red[] reuse safety
    if (lane == 0) red[warp] = sum;
    __syncthreads();
    if (tid < 8) {
        float t = red[tid];
#pragma unroll
        for (int off = 4; off; off >>= 1)
            t += __shfl_xor_sync(0xffu, t, off);
        if (tid == 0) s_bcast = t;
    }
    __syncthreads();
    const float inv = 1.0f / s_bcast;

#pragma unroll
    for (int i = 0; i < 8; i++) v[i] *= inv;
    *(float4*)(row + tid * 8)     = *(const float4*)(v);
    *(float4*)(row + tid * 8 + 4) = *(const float4*)(v + 4);
}

// ---------------------------------------------------------------------------
// Kernel 4: out = (P @ V) * mask[:, :, None], per batch.
// grid (512/128=4, 2048/128=16, 8), 256 threads
// ---------------------------------------------------------------------------
__global__ __launch_bounds__(256) void pv_kernel(const float* __restrict__ mask,
                                                 float* __restrict__ out) {
    const int b = blockIdx.z;
    const float* P = g_s + (size_t)b * Sq * Sq;
    const float* V = g_v + (size_t)b * Sq * Dd;

    float acc[8][8];
    gemm_main<false>(P, V, Sq, Sq, Dd, acc);

    const int m0 = blockIdx.y * 128, n0 = blockIdx.x * 128;
    const int ty = threadIdx.x >> 4, tx = threadIdx.x & 15;
#pragma unroll
    for (int i = 0; i < 8; i++) {
        const int m = m0 + ty * 8 + i;
        const float mk = mask[b * Sq + m];
#pragma unroll
        for (int j = 0; j < 8; j += 4) {
            const int n = n0 + tx * 8 + j;
            float4 r;
            r.x = acc[i][j + 0] * mk;
            r.y = acc[i][j + 1] * mk;
            r.z = acc[i][j + 2] * mk;
            r.w = acc[i][j + 3] * mk;
            *(float4*)(out + ((size_t)b * Sq + m) * Dd + n) = r;
        }
    }
}

// ---------------------------------------------------------------------------
// Launch: x, attention_mask, Wq, bq, Wk, bk, Wv, bv  ->  out [B,S,D] fp32
// ---------------------------------------------------------------------------
extern "C" void kernel_launch(void* const* d_in, const int* in_sizes, int n_in,
                              void* d_out, int out_size) {
    const float* x    = (const float*)d_in[0];
    const float* mask = (const float*)d_in[1];
    const float* Wq   = (const float*)d_in[2];
    const float* bq   = (const float*)d_in[3];
    const float* Wk   = (const float*)d_in[4];
    const float* bk   = (const float*)d_in[5];
    const float* Wv   = (const float*)d_in[6];
    const float* bv   = (const float*)d_in[7];
    float* out = (float*)d_out;

    dim3 blk(256);
    qkv_proj_kernel<<<dim3(Dd / 128, (Bsz * Sq) / 128, 3), blk>>>(
        x, Wq, bq, Wk, bk, Wv, bv);
    scores_kernel<<<dim3(Sq / 128, Sq / 128, Bsz), blk>>>();
    softmax_kernel<<<dim3(Sq, Bsz), blk>>>();
    pv_kernel<<<dim3(Dd / 128, Sq / 128, Bsz), blk>>>(mask, out);
}

// round 3
// speedup vs baseline: 2.2229x; 2.2229x over previous
#include <cuda_runtime.h>
#include <cstdint>

#define Bsz 8
#define Sq  2048
#define Dd  512

// ---------------------------------------------------------------------------
// Scratch (__device__ globals; allocation-free rule)
// ---------------------------------------------------------------------------
__device__ float g_q [Bsz * Sq * Dd];
__device__ float g_k [Bsz * Sq * Dd];
__device__ float g_v [Bsz * Sq * Dd];
__device__ float g_vt[Bsz * Dd * Sq];          // V^T per batch: [d][s]
__device__ float g_wt[3 * Dd * Dd];            // Wq^T, Wk^T, Wv^T
__device__ float g_s [(size_t)Bsz * Sq * Sq];  // scores / attn probs

__device__ __forceinline__ uint32_t tf32r(float f) {
    uint32_t u;
    asm("cvt.rna.tf32.f32 %0, %1;" : "=r"(u) : "f"(f));
    return u;
}

__device__ __forceinline__ void mma8(float (&d)[4], const uint32_t (&a)[4],
                                     const uint32_t (&b)[2]) {
    asm volatile(
        "mma.sync.aligned.m16n8k8.row.col.f32.tf32.tf32.f32 "
        "{%0,%1,%2,%3}, {%4,%5,%6,%7}, {%8,%9}, {%0,%1,%2,%3};"
        : "+f"(d[0]), "+f"(d[1]), "+f"(d[2]), "+f"(d[3])
        : "r"(a[0]), "r"(a[1]), "r"(a[2]), "r"(a[3]), "r"(b[0]), "r"(b[1]));
}

// ---------------------------------------------------------------------------
// 128x128x16 tensor-core GEMM body. 256 threads = 8 warps (4m x 2n),
// warp tile 32x64, mma.m16n8k8 tf32. A: [M,K] rm, B: [N,K] rm.
// SMEM stride 17 floats -> conflict-free fragment LDS.
// ---------------------------------------------------------------------------
#define SLD 17

struct GemmSmem {
    uint32_t sA[128 * SLD];
    uint32_t sB[128 * SLD];
};

__device__ __forceinline__ void gemm_mma(const float* __restrict__ gA,
                                         const float* __restrict__ gB,
                                         int K, int lda, int ldb,
                                         float (&acc)[2][8][4]) {
    __shared__ GemmSmem sm;
    const int tid = threadIdx.x;
    const int m0 = blockIdx.y * 128, n0 = blockIdx.x * 128;
    const int warp = tid >> 5, lane = tid & 31;
    const int wm = warp & 3, wn = warp >> 2;

    // loader: 128 rows x 16 floats = 512 float4 per tile; 2 per thread
    const int lr0 = tid >> 2;            // 0..63
    const int lr1 = lr0 + 64;            // 64..127
    const int lc  = (tid & 3) * 4;       // 0,4,8,12

#pragma unroll
    for (int mt = 0; mt < 2; mt++)
#pragma unroll
        for (int nt = 0; nt < 8; nt++)
#pragma unroll
            for (int i = 0; i < 4; i++) acc[mt][nt][i] = 0.0f;

    float4 pa0, pa1, pb0, pb1;

    auto loadg = [&](int k0) {
        pa0 = *(const float4*)(gA + (size_t)(m0 + lr0) * lda + k0 + lc);
        pa1 = *(const float4*)(gA + (size_t)(m0 + lr1) * lda + k0 + lc);
        pb0 = *(const float4*)(gB + (size_t)(n0 + lr0) * ldb + k0 + lc);
        pb1 = *(const float4*)(gB + (size_t)(n0 + lr1) * ldb + k0 + lc);
    };
    auto stores = [&]() {
        sm.sA[lr0 * SLD + lc + 0] = tf32r(pa0.x);
        sm.sA[lr0 * SLD + lc + 1] = tf32r(pa0.y);
        sm.sA[lr0 * SLD + lc + 2] = tf32r(pa0.z);
        sm.sA[lr0 * SLD + lc + 3] = tf32r(pa0.w);
        sm.sA[lr1 * SLD + lc + 0] = tf32r(pa1.x);
        sm.sA[lr1 * SLD + lc + 1] = tf32r(pa1.y);
        sm.sA[lr1 * SLD + lc + 2] = tf32r(pa1.z);
        sm.sA[lr1 * SLD + lc + 3] = tf32r(pa1.w);
        sm.sB[lr0 * SLD + lc + 0] = tf32r(pb0.x);
        sm.sB[lr0 * SLD + lc + 1] = tf32r(pb0.y);
        sm.sB[lr0 * SLD + lc + 2] = tf32r(pb0.z);
        sm.sB[lr0 * SLD + lc + 3] = tf32r(pb0.w);
        sm.sB[lr1 * SLD + lc + 0] = tf32r(pb1.x);
        sm.sB[lr1 * SLD + lc + 1] = tf32r(pb1.y);
        sm.sB[lr1 * SLD + lc + 2] = tf32r(pb1.z);
        sm.sB[lr1 * SLD + lc + 3] = tf32r(pb1.w);
    };
    auto compute = [&]() {
#pragma unroll
        for (int ks = 0; ks < 2; ks++) {
            const int kb = ks * 8;
            uint32_t af[2][4];
            uint32_t bf[8][2];
#pragma unroll
            for (int mt = 0; mt < 2; mt++) {
                const int row = wm * 32 + mt * 16 + (lane >> 2);
                const int col = kb + (lane & 3);
                af[mt][0] = sm.sA[row * SLD + col];
                af[mt][1] = sm.sA[(row + 8) * SLD + col];
                af[mt][2] = sm.sA[row * SLD + col + 4];
                af[mt][3] = sm.sA[(row + 8) * SLD + col + 4];
            }
#pragma unroll
            for (int nt = 0; nt < 8; nt++) {
                const int nrow = wn * 64 + nt * 8 + (lane >> 2);
                const int col = kb + (lane & 3);
                bf[nt][0] = sm.sB[nrow * SLD + col];
                bf[nt][1] = sm.sB[nrow * SLD + col + 4];
            }
#pragma unroll
            for (int mt = 0; mt < 2; mt++)
#pragma unroll
                for (int nt = 0; nt < 8; nt++)
                    mma8(acc[mt][nt], af[mt], bf[nt]);
        }
    };

    const int NC = K >> 4;
    loadg(0);
    stores();
    __syncthreads();
    for (int c = 1; c < NC; c++) {
        loadg(c * 16);      // global prefetch overlaps compute below
        compute();
        __syncthreads();
        stores();
        __syncthreads();
    }
    compute();
}

// out[r][c] = (acc * scale + bias[c]) * rowmul[r]   (bias/rowmul nullable)
__device__ __forceinline__ void store_epi(float (&acc)[2][8][4],
                                          float* __restrict__ out, int ldo,
                                          float scale,
                                          const float* __restrict__ bias,
                                          const float* __restrict__ rowmul) {
    const int tid = threadIdx.x;
    const int warp = tid >> 5, lane = tid & 31;
    const int wm = warp & 3, wn = warp >> 2;
    const int m0 = blockIdx.y * 128, n0 = blockIdx.x * 128;

#pragma unroll
    for (int mt = 0; mt < 2; mt++) {
        const int r = m0 + wm * 32 + mt * 16 + (lane >> 2);
#pragma unroll
        for (int half = 0; half < 2; half++) {
            const int rr = r + half * 8;
            const float rm = rowmul ? rowmul[rr] : 1.0f;
#pragma unroll
            for (int nt = 0; nt < 8; nt++) {
                const int cb = n0 + wn * 64 + nt * 8 + 2 * (lane & 3);
                float v0 = acc[mt][nt][half * 2 + 0] * scale;
                float v1 = acc[mt][nt][half * 2 + 1] * scale;
                if (bias) { v0 += bias[cb]; v1 += bias[cb + 1]; }
                float2 w;
                w.x = v0 * rm;
                w.y = v1 * rm;
                *(float2*)(out + (size_t)rr * ldo + cb) = w;
            }
        }
    }
}

// ---------------------------------------------------------------------------
// GEMM kernels
// ---------------------------------------------------------------------------
__global__ __launch_bounds__(256) void qkv_tc(const float* __restrict__ x,
                                              const float* __restrict__ bq,
                                              const float* __restrict__ bk,
                                              const float* __restrict__ bv) {
    const int z = blockIdx.z;
    const float* Bm = g_wt + (size_t)z * Dd * Dd;
    const float* bias = (z == 0) ? bq : (z == 1) ? bk : bv;
    float* out = (z == 0) ? g_q : (z == 1) ? g_k : g_v;
    float acc[2][8][4];
    gemm_mma(x, Bm, Dd, Dd, Dd, acc);
    store_epi(acc, out, Dd, 1.0f, bias, nullptr);
}

__global__ __launch_bounds__(256) void scores_tc() {
    const int z = blockIdx.z;
    float acc[2][8][4];
    gemm_mma(g_q + (size_t)z * Sq * Dd, g_k + (size_t)z * Sq * Dd, Dd, Dd, Dd, acc);
    store_epi(acc, g_s + (size_t)z * Sq * Sq, Sq, 0.04419417382415922f,
              nullptr, nullptr);
}

__global__ __launch_bounds__(256) void pv_tc(const float* __restrict__ mask,
                                             float* __restrict__ out) {
    const int z = blockIdx.z;
    float acc[2][8][4];
    gemm_mma(g_s + (size_t)z * Sq * Sq, g_vt + (size_t)z * Dd * Sq, Sq, Sq, Sq, acc);
    store_epi(acc, out + (size_t)z * Sq * Dd, Dd, 1.0f, nullptr, mask + z * Sq);
}

// ---------------------------------------------------------------------------
// Transposes (32x32 tiles)
// ---------------------------------------------------------------------------
__global__ __launch_bounds__(256) void transpose_w(const float* __restrict__ wq,
                                                   const float* __restrict__ wk,
                                                   const float* __restrict__ wv) {
    __shared__ float t[32][33];
    const int z = blockIdx.z;
    const float* in = (z == 0) ? wq : (z == 1) ? wk : wv;
    float* out = g_wt + (size_t)z * Dd * Dd;
    const int r0 = blockIdx.y * 32, c0 = blockIdx.x * 32;
    const int lx = threadIdx.x & 31, ly = threadIdx.x >> 5;
#pragma unroll
    for (int i = 0; i < 32; i += 8)
        t[ly + i][lx] = in[(size_t)(r0 + ly + i) * Dd + c0 + lx];
    __syncthreads();
#pragma unroll
    for (int i = 0; i < 32; i += 8)
        out[(size_t)(c0 + ly + i) * Dd + r0 + lx] = t[lx][ly + i];
}

__global__ __launch_bounds__(256) void transpose_v() {
    __shared__ float t[32][33];
    const int b = blockIdx.z;
    const float* in = g_v + (size_t)b * Sq * Dd;   // [s][d]
    float* out = g_vt + (size_t)b * Dd * Sq;       // [d][s]
    const int r0 = blockIdx.y * 32, c0 = blockIdx.x * 32;   // r=s, c=d
    const int lx = threadIdx.x & 31, ly = threadIdx.x >> 5;
#pragma unroll
    for (int i = 0; i < 32; i += 8)
        t[ly + i][lx] = in[(size_t)(r0 + ly + i) * Dd + c0 + lx];
    __syncthreads();
#pragma unroll
    for (int i = 0; i < 32; i += 8)
        out[(size_t)(c0 + ly + i) * Sq + r0 + lx] = t[lx][ly + i];
}

// ---------------------------------------------------------------------------
// Softmax over rows of g_s. One 256-thread block per row.
// ---------------------------------------------------------------------------
__global__ __launch_bounds__(256) void softmax_kernel() {
    const int b = blockIdx.y;
    float* row = g_s + ((size_t)b * Sq + blockIdx.x) * Sq;
    const int tid = threadIdx.x;
    const int lane = tid & 31;
    const int warp = tid >> 5;

    __shared__ float red[8];
    __shared__ float s_bcast;

    float v[8];
    *(float4*)(v)     = *(const float4*)(row + tid * 8);
    *(float4*)(v + 4) = *(const float4*)(row + tid * 8 + 4);

    float m = v[0];
#pragma unroll
    for (int i = 1; i < 8; i++) m = fmaxf(m, v[i]);
#pragma unroll
    for (int off = 16; off; off >>= 1)
        m = fmaxf(m, __shfl_xor_sync(0xffffffffu, m, off));
    if (lane == 0) red[warp] = m;
    __syncthreads();
    if (tid < 8) {
        float t = red[tid];
#pragma unroll
        for (int off = 4; off; off >>= 1)
            t = fmaxf(t, __shfl_xor_sync(0xffu, t, off));
        if (tid == 0) s_bcast = t;
    }
    __syncthreads();
    const float rowmax = s_bcast;

    float sum = 0.0f;
#pragma unroll
    for (int i = 0; i < 8; i++) {
        v[i] = __expf(v[i] - rowmax);
        sum += v[i];
    }
#pragma unroll
    for (int off = 16; off; off >>= 1)
        sum += __shfl_xor_sync(0xffffffffu, sum, off);
    __syncthreads();
    if (lane == 0) red[warp] = sum;
    __syncthreads();
    if (tid < 8) {
        float t = red[tid];
#pragma unroll
        for (int off = 4; off; off >>= 1)
            t += __shfl_xor_sync(0xffu, t, off);
        if (tid == 0) s_bcast = t;
    }
    __syncthreads();
    const float inv = 1.0f / s_bcast;

#pragma unroll
    for (int i = 0; i < 8; i++) v[i] *= inv;
    *(float4*)(row + tid * 8)     = *(const float4*)(v);
    *(float4*)(row + tid * 8 + 4) = *(const float4*)(v + 4);
}

// ---------------------------------------------------------------------------
// Launch
// ---------------------------------------------------------------------------
extern "C" void kernel_launch(void* const* d_in, const int* in_sizes, int n_in,
                              void* d_out, int out_size) {
    const float* x    = (const float*)d_in[0];
    const float* mask = (const float*)d_in[1];
    const float* Wq   = (const float*)d_in[2];
    const float* bq   = (const float*)d_in[3];
    const float* Wk   = (const float*)d_in[4];
    const float* bk   = (const float*)d_in[5];
    const float* Wv   = (const float*)d_in[6];
    const float* bv   = (const float*)d_in[7];
    float* out = (float*)d_out;

    dim3 blk(256);
    transpose_w<<<dim3(16, 16, 3), blk>>>(Wq, Wk, Wv);
    qkv_tc<<<dim3(Dd / 128, (Bsz * Sq) / 128, 3), blk>>>(x, bq, bk, bv);
    transpose_v<<<dim3(Dd / 32, Sq / 32, Bsz), blk>>>();
    scores_tc<<<dim3(Sq / 128, Sq / 128, Bsz), blk>>>();
    softmax_kernel<<<dim3(Sq, Bsz), blk>>>();
    pv_tc<<<dim3(Dd / 128, Sq / 128, Bsz), blk>>>(mask, out);
}

// round 4
// speedup vs baseline: 2.8239x; 1.2704x over previous
#include <cuda_runtime.h>
#include <cstdint>

#define Bsz 8
#define Sq  2048
#define Dd  512

// ---------------------------------------------------------------------------
// Scratch (__device__ globals; allocation-free rule)
// ---------------------------------------------------------------------------
__device__ float g_q [Bsz * Sq * Dd];
__device__ float g_k [Bsz * Sq * Dd];
__device__ float g_v [Bsz * Sq * Dd];
__device__ float g_vt[Bsz * Dd * Sq];          // V^T per batch: [d][s]
__device__ float g_wt[3 * Dd * Dd];            // Wq^T, Wk^T, Wv^T
__device__ float g_s [(size_t)Bsz * Sq * Sq];  // scores / attn probs

__device__ __forceinline__ uint32_t tf32r(float f) {
    uint32_t u;
    asm("cvt.rna.tf32.f32 %0, %1;" : "=r"(u) : "f"(f));
    return u;
}

__device__ __forceinline__ void mma8(float (&d)[4], const uint32_t (&a)[4],
                                     const uint32_t (&b)[2]) {
    asm volatile(
        "mma.sync.aligned.m16n8k8.row.col.f32.tf32.tf32.f32 "
        "{%0,%1,%2,%3}, {%4,%5,%6,%7}, {%8,%9}, {%0,%1,%2,%3};"
        : "+f"(d[0]), "+f"(d[1]), "+f"(d[2]), "+f"(d[3])
        : "r"(a[0]), "r"(a[1]), "r"(a[2]), "r"(a[3]), "r"(b[0]), "r"(b[1]));
}

// ---------------------------------------------------------------------------
// 128x128x16 tensor-core GEMM body. 256 threads = 8 warps (4m x 2n),
// warp tile 32x64, mma.m16n8k8 tf32. A: [M,K] rm, B: [N,K] rm.
// SMEM stride 20 words: frag-load banks 4*(5g mod 8)+c -> conflict-free.
// Double-buffered staging, one barrier per k-chunk.
// ---------------------------------------------------------------------------
#define SLD 20

__device__ __forceinline__ void gemm_mma(const float* __restrict__ gA,
                                         const float* __restrict__ gB,
                                         int K, int lda, int ldb,
                                         float (&acc)[2][8][4]) {
    __shared__ uint32_t sA[2][128 * SLD];
    __shared__ uint32_t sB[2][128 * SLD];

    const int tid = threadIdx.x;
    const int m0 = blockIdx.y * 128, n0 = blockIdx.x * 128;
    const int warp = tid >> 5, lane = tid & 31;
    const int wm = warp & 3, wn = warp >> 2;

    // loader: 128 rows x 16 floats = 512 float4 per tile; 2 per thread
    const int lr0 = tid >> 2;            // 0..63
    const int lr1 = lr0 + 64;            // 64..127
    const int lc  = (tid & 3) * 4;       // 0,4,8,12

#pragma unroll
    for (int mt = 0; mt < 2; mt++)
#pragma unroll
        for (int nt = 0; nt < 8; nt++)
#pragma unroll
            for (int i = 0; i < 4; i++) acc[mt][nt][i] = 0.0f;

    float4 pa0, pa1, pb0, pb1;

    auto loadg = [&](int k0) {
        pa0 = *(const float4*)(gA + (size_t)(m0 + lr0) * lda + k0 + lc);
        pa1 = *(const float4*)(gA + (size_t)(m0 + lr1) * lda + k0 + lc);
        pb0 = *(const float4*)(gB + (size_t)(n0 + lr0) * ldb + k0 + lc);
        pb1 = *(const float4*)(gB + (size_t)(n0 + lr1) * ldb + k0 + lc);
    };
    auto stores = [&](int buf) {
        uint4 ua0 = make_uint4(tf32r(pa0.x), tf32r(pa0.y), tf32r(pa0.z), tf32r(pa0.w));
        uint4 ua1 = make_uint4(tf32r(pa1.x), tf32r(pa1.y), tf32r(pa1.z), tf32r(pa1.w));
        uint4 ub0 = make_uint4(tf32r(pb0.x), tf32r(pb0.y), tf32r(pb0.z), tf32r(pb0.w));
        uint4 ub1 = make_uint4(tf32r(pb1.x), tf32r(pb1.y), tf32r(pb1.z), tf32r(pb1.w));
        *(uint4*)(sA[buf] + lr0 * SLD + lc) = ua0;
        *(uint4*)(sA[buf] + lr1 * SLD + lc) = ua1;
        *(uint4*)(sB[buf] + lr0 * SLD + lc) = ub0;
        *(uint4*)(sB[buf] + lr1 * SLD + lc) = ub1;
    };
    auto compute = [&](int buf) {
        const uint32_t* __restrict__ cA = sA[buf];
        const uint32_t* __restrict__ cB = sB[buf];
#pragma unroll
        for (int ks = 0; ks < 2; ks++) {
            const int kb = ks * 8;
            uint32_t af[2][4];
            uint32_t bf[8][2];
#pragma unroll
            for (int mt = 0; mt < 2; mt++) {
                const int row = wm * 32 + mt * 16 + (lane >> 2);
                const int col = kb + (lane & 3);
                af[mt][0] = cA[row * SLD + col];
                af[mt][1] = cA[(row + 8) * SLD + col];
                af[mt][2] = cA[row * SLD + col + 4];
                af[mt][3] = cA[(row + 8) * SLD + col + 4];
            }
#pragma unroll
            for (int nt = 0; nt < 8; nt++) {
                const int nrow = wn * 64 + nt * 8 + (lane >> 2);
                const int col = kb + (lane & 3);
                bf[nt][0] = cB[nrow * SLD + col];
                bf[nt][1] = cB[nrow * SLD + col + 4];
            }
#pragma unroll
            for (int mt = 0; mt < 2; mt++)
#pragma unroll
                for (int nt = 0; nt < 8; nt++)
                    mma8(acc[mt][nt], af[mt], bf[nt]);
        }
    };

    const int NC = K >> 4;
    loadg(0);
    stores(0);
    __syncthreads();
    for (int c = 1; c < NC; c++) {
        loadg(c * 16);           // global prefetch for chunk c
        compute((c - 1) & 1);    // consume chunk c-1
        stores(c & 1);           // stage chunk c into the other buffer
        __syncthreads();
    }
    compute((NC - 1) & 1);
}

// out[r][c] = (acc * scale + bias[c]) * rowmul[r]   (bias/rowmul nullable)
__device__ __forceinline__ void store_epi(float (&acc)[2][8][4],
                                          float* __restrict__ out, int ldo,
                                          float scale,
                                          const float* __restrict__ bias,
                                          const float* __restrict__ rowmul) {
    const int tid = threadIdx.x;
    const int warp = tid >> 5, lane = tid & 31;
    const int wm = warp & 3, wn = warp >> 2;
    const int m0 = blockIdx.y * 128, n0 = blockIdx.x * 128;

#pragma unroll
    for (int mt = 0; mt < 2; mt++) {
        const int r = m0 + wm * 32 + mt * 16 + (lane >> 2);
#pragma unroll
        for (int half = 0; half < 2; half++) {
            const int rr = r + half * 8;
            const float rm = rowmul ? rowmul[rr] : 1.0f;
#pragma unroll
            for (int nt = 0; nt < 8; nt++) {
                const int cb = n0 + wn * 64 + nt * 8 + 2 * (lane & 3);
                float v0 = acc[mt][nt][half * 2 + 0] * scale;
                float v1 = acc[mt][nt][half * 2 + 1] * scale;
                if (bias) { v0 += bias[cb]; v1 += bias[cb + 1]; }
                float2 w;
                w.x = v0 * rm;
                w.y = v1 * rm;
                *(float2*)(out + (size_t)rr * ldo + cb) = w;
            }
        }
    }
}

// ---------------------------------------------------------------------------
// GEMM kernels
// ---------------------------------------------------------------------------
__global__ __launch_bounds__(256) void qkv_tc(const float* __restrict__ x,
                                              const float* __restrict__ bq,
                                              const float* __restrict__ bk,
                                              const float* __restrict__ bv) {
    const int z = blockIdx.z;
    const float* Bm = g_wt + (size_t)z * Dd * Dd;
    const float* bias = (z == 0) ? bq : (z == 1) ? bk : bv;
    float* out = (z == 0) ? g_q : (z == 1) ? g_k : g_v;
    float acc[2][8][4];
    gemm_mma(x, Bm, Dd, Dd, Dd, acc);
    store_epi(acc, out, Dd, 1.0f, bias, nullptr);
}

__global__ __launch_bounds__(256) void scores_tc() {
    const int z = blockIdx.z;
    float acc[2][8][4];
    gemm_mma(g_q + (size_t)z * Sq * Dd, g_k + (size_t)z * Sq * Dd, Dd, Dd, Dd, acc);
    store_epi(acc, g_s + (size_t)z * Sq * Sq, Sq, 0.04419417382415922f,
              nullptr, nullptr);
}

__global__ __launch_bounds__(256) void pv_tc(const float* __restrict__ mask,
                                             float* __restrict__ out) {
    const int z = blockIdx.z;
    float acc[2][8][4];
    gemm_mma(g_s + (size_t)z * Sq * Sq, g_vt + (size_t)z * Dd * Sq, Sq, Sq, Sq, acc);
    store_epi(acc, out + (size_t)z * Sq * Dd, Dd, 1.0f, nullptr, mask + z * Sq);
}

// ---------------------------------------------------------------------------
// Transposes (32x32 tiles)
// ---------------------------------------------------------------------------
__global__ __launch_bounds__(256) void transpose_w(const float* __restrict__ wq,
                                                   const float* __restrict__ wk,
                                                   const float* __restrict__ wv) {
    __shared__ float t[32][33];
    const int z = blockIdx.z;
    const float* in = (z == 0) ? wq : (z == 1) ? wk : wv;
    float* out = g_wt + (size_t)z * Dd * Dd;
    const int r0 = blockIdx.y * 32, c0 = blockIdx.x * 32;
    const int lx = threadIdx.x & 31, ly = threadIdx.x >> 5;
#pragma unroll
    for (int i = 0; i < 32; i += 8)
        t[ly + i][lx] = in[(size_t)(r0 + ly + i) * Dd + c0 + lx];
    __syncthreads();
#pragma unroll
    for (int i = 0; i < 32; i += 8)
        out[(size_t)(c0 + ly + i) * Dd + r0 + lx] = t[lx][ly + i];
}

__global__ __launch_bounds__(256) void transpose_v() {
    __shared__ float t[32][33];
    const int b = blockIdx.z;
    const float* in = g_v + (size_t)b * Sq * Dd;   // [s][d]
    float* out = g_vt + (size_t)b * Dd * Sq;       // [d][s]
    const int r0 = blockIdx.y * 32, c0 = blockIdx.x * 32;   // r=s, c=d
    const int lx = threadIdx.x & 31, ly = threadIdx.x >> 5;
#pragma unroll
    for (int i = 0; i < 32; i += 8)
        t[ly + i][lx] = in[(size_t)(r0 + ly + i) * Dd + c0 + lx];
    __syncthreads();
#pragma unroll
    for (int i = 0; i < 32; i += 8)
        out[(size_t)(c0 + ly + i) * Sq + r0 + lx] = t[lx][ly + i];
}

// ---------------------------------------------------------------------------
// Softmax over rows of g_s. One 256-thread block per row.
// ---------------------------------------------------------------------------
__global__ __launch_bounds__(256) void softmax_kernel() {
    const int b = blockIdx.y;
    float* row = g_s + ((size_t)b * Sq + blockIdx.x) * Sq;
    const int tid = threadIdx.x;
    const int lane = tid & 31;
    const int warp = tid >> 5;

    __shared__ float red[8];
    __shared__ float s_bcast;

    float v[8];
    *(float4*)(v)     = *(const float4*)(row + tid * 8);
    *(float4*)(v + 4) = *(const float4*)(row + tid * 8 + 4);

    float m = v[0];
#pragma unroll
    for (int i = 1; i < 8; i++) m = fmaxf(m, v[i]);
#pragma unroll
    for (int off = 16; off; off >>= 1)
        m = fmaxf(m, __shfl_xor_sync(0xffffffffu, m, off));
    if (lane == 0) red[warp] = m;
    __syncthreads();
    if (tid < 8) {
        float t = red[tid];
#pragma unroll
        for (int off = 4; off; off >>= 1)
            t = fmaxf(t, __shfl_xor_sync(0xffu, t, off));
        if (tid == 0) s_bcast = t;
    }
    __syncthreads();
    const float rowmax = s_bcast;

    float sum = 0.0f;
#pragma unroll
    for (int i = 0; i < 8; i++) {
        v[i] = __expf(v[i] - rowmax);
        sum += v[i];
    }
#pragma unroll
    for (int off = 16; off; off >>= 1)
        sum += __shfl_xor_sync(0xffffffffu, sum, off);
    __syncthreads();
    if (lane == 0) red[warp] = sum;
    __syncthreads();
    if (tid < 8) {
        float t = red[tid];
#pragma unroll
        for (int off = 4; off; off >>= 1)
            t += __shfl_xor_sync(0xffu, t, off);
        if (tid == 0) s_bcast = t;
    }
    __syncthreads();
    const float inv = 1.0f / s_bcast;

#pragma unroll
    for (int i = 0; i < 8; i++) v[i] *= inv;
    *(float4*)(row + tid * 8)     = *(const float4*)(v);
    *(float4*)(row + tid * 8 + 4) = *(const float4*)(v + 4);
}

// ---------------------------------------------------------------------------
// Launch
// ---------------------------------------------------------------------------
extern "C" void kernel_launch(void* const* d_in, const int* in_sizes, int n_in,
                              void* d_out, int out_size) {
    const float* x    = (const float*)d_in[0];
    const float* mask = (const float*)d_in[1];
    const float* Wq   = (const float*)d_in[2];
    const float* bq   = (const float*)d_in[3];
    const float* Wk   = (const float*)d_in[4];
    const float* bk   = (const float*)d_in[5];
    const float* Wv   = (const float*)d_in[6];
    const float* bv   = (const float*)d_in[7];
    float* out = (float*)d_out;

    dim3 blk(256);
    transpose_w<<<dim3(16, 16, 3), blk>>>(Wq, Wk, Wv);
    qkv_tc<<<dim3(Dd / 128, (Bsz * Sq) / 128, 3), blk>>>(x, bq, bk, bv);
    transpose_v<<<dim3(Dd / 32, Sq / 32, Bsz), blk>>>();
    scores_tc<<<dim3(Sq / 128, Sq / 128, Bsz), blk>>>();
    softmax_kernel<<<dim3(Sq, Bsz), blk>>>();
    pv_tc<<<dim3(Dd / 128, Sq / 128, Bsz), blk>>>(mask, out);
}

// round 6
// speedup vs baseline: 3.2555x; 1.1528x over previous
#include <cuda_runtime.h>
#include <cstdint>

#define Bsz 8
#define Sq  2048
#define Dd  512

// ---------------------------------------------------------------------------
// Scratch (__device__ globals; allocation-free rule)
// ---------------------------------------------------------------------------
__device__ float g_q [Bsz * Sq * Dd];
__device__ float g_k [Bsz * Sq * Dd];
__device__ float g_v [Bsz * Sq * Dd];
__device__ float g_vt[Bsz * Dd * Sq];          // V^T per batch: [d][s]
__device__ float g_wt[3 * Dd * Dd];            // Wq^T, Wk^T, Wv^T
__device__ float g_s [(size_t)Bsz * Sq * Sq];  // scores / attn probs

__device__ __forceinline__ uint32_t tf32r(float f) {
    uint32_t u;
    asm("cvt.rna.tf32.f32 %0, %1;" : "=r"(u) : "f"(f));
    return u;
}

__device__ __forceinline__ void mma8(float (&d)[4], const uint32_t (&a)[4],
                                     const uint32_t* b) {
    asm volatile(
        "mma.sync.aligned.m16n8k8.row.col.f32.tf32.tf32.f32 "
        "{%0,%1,%2,%3}, {%4,%5,%6,%7}, {%8,%9}, {%0,%1,%2,%3};"
        : "+f"(d[0]), "+f"(d[1]), "+f"(d[2]), "+f"(d[3])
        : "r"(a[0]), "r"(a[1]), "r"(a[2]), "r"(a[3]), "r"(b[0]), "r"(b[1]));
}

__device__ __forceinline__ void ldsm4(uint32_t& r0, uint32_t& r1, uint32_t& r2,
                                      uint32_t& r3, uint32_t addr) {
    asm volatile(
        "ldmatrix.sync.aligned.m8n8.x4.shared.b16 {%0,%1,%2,%3}, [%4];"
        : "=r"(r0), "=r"(r1), "=r"(r2), "=r"(r3) : "r"(addr));
}

// Swizzled byte offset of 16B group g (0..3) in row r (row = 16 words = 64B).
// slot16(r,g) = r*4 + (g ^ ((r>>1)&3)) -> LDSM tiles & STS.128 conflict-free.
__device__ __forceinline__ uint32_t swz(int r, int g) {
    return (uint32_t)(r * 64 + ((g ^ ((r >> 1) & 3)) << 4));
}

// ---------------------------------------------------------------------------
// 128x128x16 tensor-core GEMM body. 256 threads = 8 warps (4m x 2n),
// warp tile 32x64, mma.m16n8k8 tf32. A: [M,K] rm, B: [N,K] rm.
// ldmatrix.x4 fragment loads; double-buffered staging (2x16KB).
// ---------------------------------------------------------------------------
__device__ __forceinline__ void gemm_mma(const float* __restrict__ gA,
                                         const float* __restrict__ gB,
                                         int K, int lda, int ldb,
                                         float (&acc)[2][8][4]) {
    __shared__ uint32_t sA[2][128 * 16];
    __shared__ uint32_t sB[2][128 * 16];

    const int tid = threadIdx.x;
    const int m0 = blockIdx.y * 128, n0 = blockIdx.x * 128;
    const int warp = tid >> 5, lane = tid & 31;
    const int wm = warp & 3, wn = warp >> 2;

    // staging: 128 rows x 16 floats; 2 x 16B per thread per matrix
    const int lr0 = tid >> 2;            // 0..63
    const int lr1 = lr0 + 64;
    const int lg  = tid & 3;             // 16B group
    const uint32_t st0 = swz(lr0, lg);
    const uint32_t st1 = swz(lr1, lg);

    // ldmatrix per-lane source addresses (byte offsets, ks=0)
    const int ti = lane & 7;             // row within tile
    const int tt = lane >> 3;            // tile index 0..3
    uint32_t offA[2], offB[4];
#pragma unroll
    for (int mt = 0; mt < 2; mt++) {
        const int r = wm * 32 + mt * 16 + (tt & 1) * 8 + ti;
        offA[mt] = swz(r, tt >> 1);
    }
#pragma unroll
    for (int p = 0; p < 4; p++) {
        const int n = wn * 64 + p * 16 + (tt >> 1) * 8 + ti;
        offB[p] = swz(n, tt & 1);
    }

#pragma unroll
    for (int mt = 0; mt < 2; mt++)
#pragma unroll
        for (int nt = 0; nt < 8; nt++)
#pragma unroll
            for (int i = 0; i < 4; i++) acc[mt][nt][i] = 0.0f;

    float4 pa0, pa1, pb0, pb1;

    auto loadg = [&](int k0) {
        pa0 = *(const float4*)(gA + (size_t)(m0 + lr0) * lda + k0 + lg * 4);
        pa1 = *(const float4*)(gA + (size_t)(m0 + lr1) * lda + k0 + lg * 4);
        pb0 = *(const float4*)(gB + (size_t)(n0 + lr0) * ldb + k0 + lg * 4);
        pb1 = *(const float4*)(gB + (size_t)(n0 + lr1) * ldb + k0 + lg * 4);
    };
    auto stores = [&](int buf) {
        uint4 ua0 = make_uint4(tf32r(pa0.x), tf32r(pa0.y), tf32r(pa0.z), tf32r(pa0.w));
        uint4 ua1 = make_uint4(tf32r(pa1.x), tf32r(pa1.y), tf32r(pa1.z), tf32r(pa1.w));
        uint4 ub0 = make_uint4(tf32r(pb0.x), tf32r(pb0.y), tf32r(pb0.z), tf32r(pb0.w));
        uint4 ub1 = make_uint4(tf32r(pb1.x), tf32r(pb1.y), tf32r(pb1.z), tf32r(pb1.w));
        *(uint4*)((char*)sA[buf] + st0) = ua0;
        *(uint4*)((char*)sA[buf] + st1) = ua1;
        *(uint4*)((char*)sB[buf] + st0) = ub0;
        *(uint4*)((char*)sB[buf] + st1) = ub1;
    };
    auto compute = [&](int buf) {
        const uint32_t baseA = (uint32_t)__cvta_generic_to_shared(sA[buf]);
        const uint32_t baseB = (uint32_t)__cvta_generic_to_shared(sB[buf]);
#pragma unroll
        for (int ks = 0; ks < 2; ks++) {
            const uint32_t kx = ks * 32;   // ks=1: XOR 32B (k-cols 4..7)
            uint32_t af[2][4];
            uint32_t bf[8][2];
            ldsm4(af[0][0], af[0][1], af[0][2], af[0][3], baseA + (offA[0] ^ kx));
            ldsm4(af[1][0], af[1][1], af[1][2], af[1][3], baseA + (offA[1] ^ kx));
#pragma unroll
            for (int p = 0; p < 4; p++)
                ldsm4(bf[2 * p][0], bf[2 * p][1], bf[2 * p + 1][0], bf[2 * p + 1][1],
                      baseB + (offB[p] ^ kx));
#pragma unroll
            for (int mt = 0; mt < 2; mt++)
#pragma unroll
                for (int nt = 0; nt < 8; nt++)
                    mma8(acc[mt][nt], af[mt], bf[nt]);
        }
    };

    const int NC = K >> 4;
    loadg(0);
    stores(0);
    __syncthreads();
    for (int c = 1; c < NC; c++) {
        loadg(c * 16);           // global prefetch for chunk c
        compute((c - 1) & 1);    // consume chunk c-1
        stores(c & 1);           // stage chunk c into the other buffer
        __syncthreads();
    }
    compute((NC - 1) & 1);
}

// out[r][c] = (acc * scale + bias[c]) * rowmul[r]   (bias/rowmul nullable)
__device__ __forceinline__ void store_epi(float (&acc)[2][8][4],
                                          float* __restrict__ out, int ldo,
                                          float scale,
                                          const float* __restrict__ bias,
                                          const float* __restrict__ rowmul) {
    const int tid = threadIdx.x;
    const int warp = tid >> 5, lane = tid & 31;
    const int wm = warp & 3, wn = warp >> 2;
    const int m0 = blockIdx.y * 128, n0 = blockIdx.x * 128;

#pragma unroll
    for (int mt = 0; mt < 2; mt++) {
        const int r = m0 + wm * 32 + mt * 16 + (lane >> 2);
#pragma unroll
        for (int half = 0; half < 2; half++) {
            const int rr = r + half * 8;
            const float rm = rowmul ? rowmul[rr] : 1.0f;
#pragma unroll
            for (int nt = 0; nt < 8; nt++) {
                const int cb = n0 + wn * 64 + nt * 8 + 2 * (lane & 3);
                float v0 = acc[mt][nt][half * 2 + 0] * scale;
                float v1 = acc[mt][nt][half * 2 + 1] * scale;
                if (bias) { v0 += bias[cb]; v1 += bias[cb + 1]; }
                float2 w;
                w.x = v0 * rm;
                w.y = v1 * rm;
                *(float2*)(out + (size_t)rr * ldo + cb) = w;
            }
        }
    }
}

// ---------------------------------------------------------------------------
// GEMM kernels
// ---------------------------------------------------------------------------
__global__ __launch_bounds__(256, 2) void qkv_tc(const float* __restrict__ x,
                                                 const float* __restrict__ bq,
                                                 const float* __restrict__ bk,
                                                 const float* __restrict__ bv) {
    const int z = blockIdx.z;
    const float* Bm = g_wt + (size_t)z * Dd * Dd;
    const float* bias = (z == 0) ? bq : (z == 1) ? bk : bv;
    float* out = (z == 0) ? g_q : (z == 1) ? g_k : g_v;
    float acc[2][8][4];
    gemm_mma(x, Bm, Dd, Dd, Dd, acc);
    store_epi(acc, out, Dd, 1.0f, bias, nullptr);
}

__global__ __launch_bounds__(256, 2) void scores_tc() {
    const int z = blockIdx.z;
    float acc[2][8][4];
    gemm_mma(g_q + (size_t)z * Sq * Dd, g_k + (size_t)z * Sq * Dd, Dd, Dd, Dd, acc);
    store_epi(acc, g_s + (size_t)z * Sq * Sq, Sq, 0.04419417382415922f,
              nullptr, nullptr);
}

__global__ __launch_bounds__(256, 2) void pv_tc(const float* __restrict__ mask,
                                                float* __restrict__ out) {
    const int z = blockIdx.z;
    float acc[2][8][4];
    gemm_mma(g_s + (size_t)z * Sq * Sq, g_vt + (size_t)z * Dd * Sq, Sq, Sq, Sq, acc);
    store_epi(acc, out + (size_t)z * Sq * Dd, Dd, 1.0f, nullptr, mask + z * Sq);
}

// ---------------------------------------------------------------------------
// Transposes (32x32 tiles)
// ---------------------------------------------------------------------------
__global__ __launch_bounds__(256) void transpose_w(const float* __restrict__ wq,
                                                   const float* __restrict__ wk,
                                                   const float* __restrict__ wv) {
    __shared__ float t[32][33];
    const int z = blockIdx.z;
    const float* in = (z == 0) ? wq : (z == 1) ? wk : wv;
    float* out = g_wt + (size_t)z * Dd * Dd;
    const int r0 = blockIdx.y * 32, c0 = blockIdx.x * 32;
    const int lx = threadIdx.x & 31, ly = threadIdx.x >> 5;
#pragma unroll
    for (int i = 0; i < 32; i += 8)
        t[ly + i][lx] = in[(size_t)(r0 + ly + i) * Dd + c0 + lx];
    __syncthreads();
#pragma unroll
    for (int i = 0; i < 32; i += 8)
        out[(size_t)(c0 + ly + i) * Dd + r0 + lx] = t[lx][ly + i];
}

__global__ __launch_bounds__(256) void transpose_v() {
    __shared__ float t[32][33];
    const int b = blockIdx.z;
    const float* in = g_v + (size_t)b * Sq * Dd;   // [s][d]
    float* out = g_vt + (size_t)b * Dd * Sq;       // [d][s]
    const int r0 = blockIdx.y * 32, c0 = blockIdx.x * 32;   // r=s, c=d
    const int lx = threadIdx.x & 31, ly = threadIdx.x >> 5;
#pragma unroll
    for (int i = 0; i < 32; i += 8)
        t[ly + i][lx] = in[(size_t)(r0 + ly + i) * Dd + c0 + lx];
    __syncthreads();
#pragma unroll
    for (int i = 0; i < 32; i += 8)
        out[(size_t)(c0 + ly + i) * Sq + r0 + lx] = t[lx][ly + i];
}

// ---------------------------------------------------------------------------
// Softmax over rows of g_s. One 256-thread block per row.
// ---------------------------------------------------------------------------
__global__ __launch_bounds__(256) void softmax_kernel() {
    const int b = blockIdx.y;
    float* row = g_s + ((size_t)b * Sq + blockIdx.x) * Sq;
    const int tid = threadIdx.x;
    const int lane = tid & 31;
    const int warp = tid >> 5;

    __shared__ float red[8];
    __shared__ float s_bcast;

    float v[8];
    *(float4*)(v)     = *(const float4*)(row + tid * 8);
    *(float4*)(v + 4) = *(const float4*)(row + tid * 8 + 4);

    float m = v[0];
#pragma unroll
    for (int i = 1; i < 8; i++) m = fmaxf(m, v[i]);
#pragma unroll
    for (int off = 16; off; off >>= 1)
        m = fmaxf(m, __shfl_xor_sync(0xffffffffu, m, off));
    if (lane == 0) red[warp] = m;
    __syncthreads();
    if (tid < 8) {
        float t = red[tid];
#pragma unroll
        for (int off = 4; off; off >>= 1)
            t = fmaxf(t, __shfl_xor_sync(0xffu, t, off));
        if (tid == 0) s_bcast = t;
    }
    __syncthreads();
    const float rowmax = s_bcast;

    float sum = 0.0f;
#pragma unroll
    for (int i = 0; i < 8; i++) {
        v[i] = __expf(v[i] - rowmax);
        sum += v[i];
    }
#pragma unroll
    for (int off = 16; off; off >>= 1)
        sum += __shfl_xor_sync(0xffffffffu, sum, off);
    __syncthreads();
    if (lane == 0) red[warp] = sum;
    __syncthreads();
    if (tid < 8) {
        float t = red[tid];
#pragma unroll
        for (int off = 4; off; off >>= 1)
            t += __shfl_xor_sync(0xffu, t, off);
        if (tid == 0) s_bcast = t;
    }
    __syncthreads();
    const float inv = 1.0f / s_bcast;

#pragma unroll
    for (int i = 0; i < 8; i++) v[i] *= inv;
    *(float4*)(row + tid * 8)     = *(const float4*)(v);
    *(float4*)(row + tid * 8 + 4) = *(const float4*)(v + 4);
}

// ---------------------------------------------------------------------------
// Launch
// ---------------------------------------------------------------------------
extern "C" void kernel_launch(void* const* d_in, const int* in_sizes, int n_in,
                              void* d_out, int out_size) {
    const float* x    = (const float*)d_in[0];
    const float* mask = (const float*)d_in[1];
    const float* Wq   = (const float*)d_in[2];
    const float* bq   = (const float*)d_in[3];
    const float* Wk   = (const float*)d_in[4];
    const float* bk   = (const float*)d_in[5];
    const float* Wv   = (const float*)d_in[6];
    const float* bv   = (const float*)d_in[7];
    float* out = (float*)d_out;

    dim3 blk(256);
    transpose_w<<<dim3(16, 16, 3), blk>>>(Wq, Wk, Wv);
    qkv_tc<<<dim3(Dd / 128, (Bsz * Sq) / 128, 3), blk>>>(x, bq, bk, bv);
    transpose_v<<<dim3(Dd / 32, Sq / 32, Bsz), blk>>>();
    scores_tc<<<dim3(Sq / 128, Sq / 128, Bsz), blk>>>();
    softmax_kernel<<<dim3(Sq, Bsz), blk>>>();
    pv_tc<<<dim3(Dd / 128, Sq / 128, Bsz), blk>>>(mask, out);
}